// round 1
// baseline (speedup 1.0000x reference)
#include <cuda_runtime.h>
#include <cstdint>

// Problem constants (match reference setup_inputs)
#define BB   8
#define SS   4096
#define DD   1024
#define KK   128
#define MM   (BB * SS)      // 32768 rows
#define LN_EPS 1e-5f

// ---------------- scratch (static device arrays; no allocations) ----------------
__device__ float g_beta [ (size_t)BB * SS * KK ];   // (B,S,K)   16 MB
__device__ float g_srseq[ (size_t)SS * BB * KK ];   // (S,B,K)   16 MB
__device__ float g_y    [ (size_t)SS * BB * DD ];   // (S*B, D) 128 MB

// =====================================================================
// SGEMM: C[M,N] = A[M,Kd] * Bt[N,Kd]^T (+ bias[n])
// block tile 128x128, 256 threads, 8x8 per-thread microtile, Kc=32
// =====================================================================
template<int KC>
__global__ __launch_bounds__(256)
void sgemm_tn(const float* __restrict__ A, const float* __restrict__ Bt,
              float* __restrict__ C, const float* __restrict__ bias,
              int M, int N, int Kd)
{
    __shared__ float As[KC][128];
    __shared__ float Bs[KC][128];

    const int bm = blockIdx.x * 128;
    const int bn = blockIdx.y * 128;
    const int tid = threadIdx.x;
    const int tx = tid & 15;        // 16 col-groups
    const int ty = tid >> 4;        // 16 row-groups

    float acc[8][8];
    #pragma unroll
    for (int i = 0; i < 8; i++)
        #pragma unroll
        for (int j = 0; j < 8; j++) acc[i][j] = 0.0f;

    const int V = KC / 4;  // float4 per row of a tile

    for (int k0 = 0; k0 < Kd; k0 += KC) {
        // load A tile (128 rows x KC cols) transposed into As[k][m]
        #pragma unroll
        for (int i = tid; i < 128 * V; i += 256) {
            int r = i / V, c4 = i % V;
            float4 v = *(const float4*)&A[(size_t)(bm + r) * Kd + k0 + c4 * 4];
            As[c4 * 4 + 0][r] = v.x;
            As[c4 * 4 + 1][r] = v.y;
            As[c4 * 4 + 2][r] = v.z;
            As[c4 * 4 + 3][r] = v.w;
        }
        // load B tile (128 rows x KC cols) transposed into Bs[k][n]
        #pragma unroll
        for (int i = tid; i < 128 * V; i += 256) {
            int r = i / V, c4 = i % V;
            float4 v = *(const float4*)&Bt[(size_t)(bn + r) * Kd + k0 + c4 * 4];
            Bs[c4 * 4 + 0][r] = v.x;
            Bs[c4 * 4 + 1][r] = v.y;
            Bs[c4 * 4 + 2][r] = v.z;
            Bs[c4 * 4 + 3][r] = v.w;
        }
        __syncthreads();

        #pragma unroll
        for (int kk = 0; kk < KC; kk++) {
            float a[8], b[8];
            #pragma unroll
            for (int i = 0; i < 8; i++) a[i] = As[kk][ty * 8 + i];
            #pragma unroll
            for (int j = 0; j < 8; j++) b[j] = Bs[kk][tx * 8 + j];
            #pragma unroll
            for (int i = 0; i < 8; i++)
                #pragma unroll
                for (int j = 0; j < 8; j++)
                    acc[i][j] = fmaf(a[i], b[j], acc[i][j]);
        }
        __syncthreads();
    }

    // epilogue
    float bias0[8];
    if (bias) {
        #pragma unroll
        for (int j = 0; j < 8; j++) bias0[j] = bias[bn + tx * 8 + j];
    } else {
        #pragma unroll
        for (int j = 0; j < 8; j++) bias0[j] = 0.0f;
    }

    #pragma unroll
    for (int i = 0; i < 8; i++) {
        const int m = bm + ty * 8 + i;
        float* crow = &C[(size_t)m * N + bn + tx * 8];
        float4 v0, v1;
        v0.x = acc[i][0] + bias0[0]; v0.y = acc[i][1] + bias0[1];
        v0.z = acc[i][2] + bias0[2]; v0.w = acc[i][3] + bias0[3];
        v1.x = acc[i][4] + bias0[4]; v1.y = acc[i][5] + bias0[5];
        v1.z = acc[i][6] + bias0[6]; v1.w = acc[i][7] + bias0[7];
        ((float4*)crow)[0] = v0;
        ((float4*)crow)[1] = v1;
    }
}

// =====================================================================
// Scan kernel: one block per batch, K threads.
// Runtime check: if R is diagonal (it is, R = 0.1*I in the dataset),
// the K x K resonance mix decouples into per-k 2x2 rotation-scales.
// Otherwise fall back to a general smem matmul path (correct, slower).
// =====================================================================
__global__ __launch_bounds__(KK)
void scan_kernel(const float* __restrict__ alpha, const float* __restrict__ omega,
                 const float* __restrict__ R,
                 float* __restrict__ srf, float* __restrict__ sif)
{
    const int b = blockIdx.x;
    const int k = threadIdx.x;

    // --- check R diagonality (cheap; R cached in L1/L2) ---
    bool ok = true;
    for (int i = k; i < KK * KK; i += KK) {
        int r = i / KK, c = i % KK;
        if (r != c && R[i] != 0.0f) ok = false;
    }
    const bool diag = (__syncthreads_and(ok) != 0);

    const float mag = 1.0f / (1.0f + expf(-alpha[k]));
    const float cth = cosf(omega[k]);
    const float sth = sinf(omega[k]);

    const float* bp = g_beta + ((size_t)b * SS) * KK + k;
    float* sp = g_srseq + (size_t)b * KK + k;

    float sr = 0.0f, si = 0.0f;

    if (diag) {
        const float dk = R[k * KK + k];
        const float Ac = dk * mag * cth;   // sr' = Ac*sr - Bc*si + dk*beta
        const float Bc = dk * mag * sth;   // si' = Bc*sr + Ac*si
        #pragma unroll 4
        for (int t = 0; t < SS; t++) {
            float gb = dk * __ldg(bp + (size_t)t * KK);
            float nr = fmaf(Ac, sr, fmaf(-Bc, si, gb));
            float ni = fmaf(Bc, sr, Ac * si);
            sr = nr; si = ni;
            sp[(size_t)t * (BB * KK)] = sr;
        }
    } else {
        // general path: full K x K mix per step via shared memory
        __shared__ float nrs[KK], nis[KK];
        for (int t = 0; t < SS; t++) {
            float bt = __ldg(bp + (size_t)t * KK);
            float nr = fmaf(mag * cth, sr, fmaf(-mag * sth, si, bt));
            float ni = mag * fmaf(sr, sth, si * cth);
            nrs[k] = nr; nis[k] = ni;
            __syncthreads();
            float a0 = 0.0f, a1 = 0.0f;
            #pragma unroll 8
            for (int j = 0; j < KK; j++) {
                float rj = R[j * KK + k];
                a0 = fmaf(nrs[j], rj, a0);
                a1 = fmaf(nis[j], rj, a1);
            }
            __syncthreads();
            sr = a0; si = a1;
            sp[(size_t)t * (BB * KK)] = sr;
        }
    }

    srf[b * KK + k] = sr;
    sif[b * KK + k] = si;
}

// =====================================================================
// LayerNorm + transpose: row r = s*B + b of g_y -> out[b][s][:]
// 256 threads, 4 floats/thread (float4)
// =====================================================================
__global__ __launch_bounds__(256)
void ln_kernel(const float* __restrict__ g, const float* __restrict__ bb,
               float* __restrict__ out)
{
    const int r = blockIdx.x;           // 0 .. S*B-1
    const int t = threadIdx.x;

    const float4 v = ((const float4*)(g_y + (size_t)r * DD))[t];

    float sum = v.x + v.y + v.z + v.w;
    float sq  = fmaf(v.x, v.x, fmaf(v.y, v.y, fmaf(v.z, v.z, v.w * v.w)));

    #pragma unroll
    for (int o = 16; o > 0; o >>= 1) {
        sum += __shfl_xor_sync(0xffffffffu, sum, o);
        sq  += __shfl_xor_sync(0xffffffffu, sq,  o);
    }

    __shared__ float ssum[8], ssq[8];
    const int w = t >> 5, ln = t & 31;
    if (ln == 0) { ssum[w] = sum; ssq[w] = sq; }
    __syncthreads();
    if (t == 0) {
        float a = 0.0f, c2 = 0.0f;
        #pragma unroll
        for (int i = 0; i < 8; i++) { a += ssum[i]; c2 += ssq[i]; }
        ssum[0] = a; ssq[0] = c2;
    }
    __syncthreads();

    const float mu  = ssum[0] * (1.0f / DD);
    const float var = ssq[0] * (1.0f / DD) - mu * mu;
    const float inv = rsqrtf(var + LN_EPS);

    const float4 gg = ((const float4*)g)[t];
    const float4 b4 = ((const float4*)bb)[t];

    float4 o;
    o.x = fmaf((v.x - mu) * inv, gg.x, b4.x);
    o.y = fmaf((v.y - mu) * inv, gg.y, b4.y);
    o.z = fmaf((v.z - mu) * inv, gg.z, b4.z);
    o.w = fmaf((v.w - mu) * inv, gg.w, b4.w);

    const int s = r >> 3;    // r = s*B + b, B=8
    const int b = r & 7;
    ((float4*)(out + ((size_t)b * SS + s) * DD))[t] = o;
}

// =====================================================================
// launch
// =====================================================================
extern "C" void kernel_launch(void* const* d_in, const int* in_sizes, int n_in,
                              void* d_out, int out_size)
{
    const float* x     = (const float*)d_in[0];  // (B,S,D)
    const float* alpha = (const float*)d_in[1];  // (K)
    const float* omega = (const float*)d_in[2];  // (K)
    const float* W_in  = (const float*)d_in[3];  // (K,D)
    const float* R     = (const float*)d_in[4];  // (K,K)
    const float* W_out = (const float*)d_in[5];  // (D,K)
    const float* b_out = (const float*)d_in[6];  // (D)
    const float* ln_g  = (const float*)d_in[7];  // (D)
    const float* ln_b  = (const float*)d_in[8];  // (D)

    float* out = (float*)d_out;                       // (B,S,D)
    float* srf = out + (size_t)BB * SS * DD;          // (B,K)
    float* sif = srf + (size_t)BB * KK;               // (B,K)

    float* beta_p;  cudaGetSymbolAddress((void**)&beta_p,  g_beta);
    float* srseq_p; cudaGetSymbolAddress((void**)&srseq_p, g_srseq);
    float* y_p;     cudaGetSymbolAddress((void**)&y_p,     g_y);

    // 1) beta = x @ W_in^T : (32768 x 1024) x (128 x 1024)^T -> (32768 x 128)
    //    x is (B,S,D) contiguous -> rows are (b,s); beta laid out (B,S,K). OK.
    {
        dim3 grid(MM / 128, KK / 128);
        sgemm_tn<32><<<grid, 256>>>(x, W_in, beta_p, nullptr, MM, KK, DD);
    }

    // 2) sequential scan -> g_srseq (S,B,K), final states -> srf/sif
    scan_kernel<<<BB, KK>>>(alpha, omega, R, srf, sif);

    // 3) y = sr_seq @ W_out^T + b_out : (32768 x 128) x (1024 x 128)^T
    //    sr_seq rows are (s,b) in that order (matches reference 'sbk' einsum).
    {
        dim3 grid(MM / 128, DD / 128);
        sgemm_tn<32><<<grid, 256>>>(srseq_p, W_out, y_p, b_out, MM, DD, KK);
    }

    // 4) LayerNorm + transpose to (B,S,D)
    ln_kernel<<<MM, 256>>>(ln_g, ln_b, out);
}

// round 3
// speedup vs baseline: 3.7829x; 3.7829x over previous
#include <cuda_runtime.h>
#include <cuda_bf16.h>
#include <cstdint>

#define BB   8
#define SS   4096
#define DD   1024
#define KK   128
#define MM   (BB * SS)
#define LN_EPS 1e-5f

// ---------------- scratch (static device arrays; no allocations) ----------------
__device__ float g_beta [ (size_t)MM * KK ];   // (B,S,K)   16 MB
__device__ float g_srseq[ (size_t)MM * KK ];   // (S,B,K)   16 MB
__device__ float g_y    [ (size_t)MM * DD ];   // (S*B, D) 128 MB

// ============================ tf32 helpers ============================
__device__ __forceinline__ uint32_t f2tf(float f) {
    uint32_t u;
    asm("cvt.rna.tf32.f32 %0, %1;" : "=r"(u) : "f"(f));
    return u;
}

#define MMA_TF32(c, a, b) \
    asm volatile("mma.sync.aligned.m16n8k8.row.col.f32.tf32.tf32.f32 " \
        "{%0,%1,%2,%3}, {%4,%5,%6,%7}, {%8,%9}, {%0,%1,%2,%3};" \
        : "+f"((c)[0]), "+f"((c)[1]), "+f"((c)[2]), "+f"((c)[3]) \
        : "r"((a)[0]), "r"((a)[1]), "r"((a)[2]), "r"((a)[3]), \
          "r"((b)[0]), "r"((b)[1]))

// ============================================================================
// tf32 tensor-core GEMM:  C[bm:+128, bn:+128] = A[128, KD] * Bt[128, KD]^T (+bias)
// 256 threads = 8 warps, warp (wm,wn) owns 64x32; K chunks of 32;
// double-buffered smem (pad 36) + register-staged global prefetch.
// ============================================================================
#define SPAD 36
#define STG_F (128 * SPAD)     // floats per tile buffer

template<int KD>
__global__ __launch_bounds__(256)
void gemm_mma(const float* __restrict__ A, const float* __restrict__ Bt,
              float* __restrict__ C, const float* __restrict__ bias, int ldc)
{
    constexpr int NCH = KD / 32;
    extern __shared__ float sm[];
    // layout: As[2][128][36], Bs[2][128][36]
    float* AsB = sm;
    float* BsB = sm + 2 * STG_F;

    const int tid = threadIdx.x;
    const int bn = blockIdx.x * 128;
    const int bm = blockIdx.y * 128;
    const int lane = tid & 31;
    const int w = tid >> 5;
    const int wm = w >> 2;       // 0..1
    const int wn = w & 3;        // 0..3

    const int ldr = tid >> 3;          // load row group base (0..31)
    const int ldc4 = tid & 7;          // float4 col (0..7)

    float acc[4][4][4];
    #pragma unroll
    for (int i = 0; i < 4; i++)
        #pragma unroll
        for (int j = 0; j < 4; j++)
            #pragma unroll
            for (int r = 0; r < 4; r++) acc[i][j][r] = 0.0f;

    const float* Ag = A + (size_t)bm * KD;
    const float* Bg = Bt + (size_t)bn * KD;

    float4 ra[4], rb[4];

    // prefetch chunk into registers
    auto prefetch = [&](int ch) {
        #pragma unroll
        for (int it = 0; it < 4; it++) {
            int r = ldr + it * 32;
            ra[it] = __ldg((const float4*)(Ag + (size_t)r * KD + ch * 32) + ldc4);
            rb[it] = __ldg((const float4*)(Bg + (size_t)r * KD + ch * 32) + ldc4);
        }
    };
    // cvt to tf32 + store staged registers to smem buffer s
    auto stage_store = [&](int s) {
        uint32_t* as = (uint32_t*)(AsB + s * STG_F);
        uint32_t* bs = (uint32_t*)(BsB + s * STG_F);
        #pragma unroll
        for (int it = 0; it < 4; it++) {
            int r = ldr + it * 32;
            uint4 va = { f2tf(ra[it].x), f2tf(ra[it].y), f2tf(ra[it].z), f2tf(ra[it].w) };
            uint4 vb = { f2tf(rb[it].x), f2tf(rb[it].y), f2tf(rb[it].z), f2tf(rb[it].w) };
            *(uint4*)(as + r * SPAD + ldc4 * 4) = va;
            *(uint4*)(bs + r * SPAD + ldc4 * 4) = vb;
        }
    };

    auto compute = [&](int s) {
        const uint32_t* as = (const uint32_t*)(AsB + s * STG_F) + (wm * 64 + (lane >> 2)) * SPAD + (lane & 3);
        const uint32_t* bs = (const uint32_t*)(BsB + s * STG_F) + (wn * 32 + (lane >> 2)) * SPAD + (lane & 3);
        #pragma unroll
        for (int ks = 0; ks < 4; ks++) {
            const int k = ks * 8;
            uint32_t a[4][4], b[4][2];
            #pragma unroll
            for (int mt = 0; mt < 4; mt++) {
                const uint32_t* p = as + mt * 16 * SPAD + k;
                a[mt][0] = p[0];
                a[mt][1] = p[8 * SPAD];
                a[mt][2] = p[4];
                a[mt][3] = p[8 * SPAD + 4];
            }
            #pragma unroll
            for (int nt = 0; nt < 4; nt++) {
                const uint32_t* p = bs + nt * 8 * SPAD + k;
                b[nt][0] = p[0];
                b[nt][1] = p[4];
            }
            #pragma unroll
            for (int mt = 0; mt < 4; mt++)
                #pragma unroll
                for (int nt = 0; nt < 4; nt++)
                    MMA_TF32(acc[mt][nt], a[mt], b[nt]);
        }
    };

    prefetch(0);
    stage_store(0);
    __syncthreads();

    for (int ch = 0; ch < NCH; ch++) {
        const int s = ch & 1;
        if (ch + 1 < NCH) prefetch(ch + 1);
        compute(s);
        __syncthreads();
        if (ch + 1 < NCH) {
            stage_store(s ^ 1);
            __syncthreads();
        }
    }

    // ---- epilogue ----
    #pragma unroll
    for (int nt = 0; nt < 4; nt++) {
        const int col = bn + wn * 32 + nt * 8 + 2 * (lane & 3);
        float2 bv;
        if (bias) bv = *(const float2*)(bias + col);
        else      bv = make_float2(0.0f, 0.0f);
        #pragma unroll
        for (int mt = 0; mt < 4; mt++) {
            const int row = bm + wm * 64 + mt * 16 + (lane >> 2);
            float2 v0 = { acc[mt][nt][0] + bv.x, acc[mt][nt][1] + bv.y };
            float2 v1 = { acc[mt][nt][2] + bv.x, acc[mt][nt][3] + bv.y };
            *(float2*)(C + (size_t)row * ldc + col) = v0;
            *(float2*)(C + (size_t)(row + 8) * ldc + col) = v1;
        }
    }
}

// ============================================================================
// Scan. Per-mode decay mag*|R_kk| (R diagonal). If all decays <= 0.5,
// chunk the sequence (CH=256) with a 64-step warmup (error <= 0.5^64).
// Runtime guards keep this exact for arbitrary inputs: scan_par no-ops
// unless (diag && decay ok); scan_serial no-ops in that case.
// ============================================================================
#define SCAN_CH   256
#define SCAN_NCH  (SS / SCAN_CH)
#define SCAN_WARM 64

__device__ __forceinline__ bool r_is_diag(const float* R, int k) {
    bool ok = true;
    for (int i = k; i < KK * KK; i += KK) {
        int r = i / KK, c = i - r * KK;
        if (r != c && R[i] != 0.0f) ok = false;
    }
    return ok;
}

__global__ __launch_bounds__(KK)
void scan_par(const float* __restrict__ alpha, const float* __restrict__ omega,
              const float* __restrict__ R,
              float* __restrict__ srf, float* __restrict__ sif)
{
    const int chunk = blockIdx.x, b = blockIdx.y, k = threadIdx.x;

    const bool diag = (__syncthreads_and(r_is_diag(R, k) ? 1 : 0) != 0);
    const float mag = 1.0f / (1.0f + expf(-alpha[k]));
    const float dk = R[k * KK + k];
    const bool dec_ok = (__syncthreads_and((mag * fabsf(dk)) <= 0.5f ? 1 : 0) != 0);
    if (!(diag && dec_ok)) return;

    const float cth = cosf(omega[k]);
    const float sth = sinf(omega[k]);
    const float Ac = dk * mag * cth;
    const float Bc = dk * mag * sth;

    const int t0 = chunk * SCAN_CH;
    const int ts = (t0 >= SCAN_WARM) ? (t0 - SCAN_WARM) : 0;

    const float* bp = g_beta + ((size_t)b * SS + ts) * KK + k;
    float sr = 0.0f, si = 0.0f;

    for (int t = ts; t < t0; t++) {          // warmup (not stored)
        float gb = dk * __ldg(bp); bp += KK;
        float nr = fmaf(Ac, sr, fmaf(-Bc, si, gb));
        float ni = fmaf(Bc, sr, Ac * si);
        sr = nr; si = ni;
    }
    float* sp = g_srseq + ((size_t)t0 * BB + b) * KK + k;
    #pragma unroll 4
    for (int t = 0; t < SCAN_CH; t++) {
        float gb = dk * __ldg(bp); bp += KK;
        float nr = fmaf(Ac, sr, fmaf(-Bc, si, gb));
        float ni = fmaf(Bc, sr, Ac * si);
        sr = nr; si = ni;
        sp[(size_t)t * (BB * KK)] = sr;
    }
    if (chunk == SCAN_NCH - 1) { srf[b * KK + k] = sr; sif[b * KK + k] = si; }
}

__global__ __launch_bounds__(KK)
void scan_serial(const float* __restrict__ alpha, const float* __restrict__ omega,
                 const float* __restrict__ R,
                 float* __restrict__ srf, float* __restrict__ sif)
{
    const int b = blockIdx.x, k = threadIdx.x;

    const bool diag = (__syncthreads_and(r_is_diag(R, k) ? 1 : 0) != 0);
    const float mag = 1.0f / (1.0f + expf(-alpha[k]));
    const float dk = R[k * KK + k];
    const bool dec_ok = (__syncthreads_and((mag * fabsf(dk)) <= 0.5f ? 1 : 0) != 0);
    if (diag && dec_ok) return;   // parallel kernel handled it

    const float cth = cosf(omega[k]);
    const float sth = sinf(omega[k]);

    const float* bp = g_beta + ((size_t)b * SS) * KK + k;
    float* sp = g_srseq + (size_t)b * KK + k;
    float sr = 0.0f, si = 0.0f;

    if (diag) {
        const float Ac = dk * mag * cth;
        const float Bc = dk * mag * sth;
        #pragma unroll 4
        for (int t = 0; t < SS; t++) {
            float gb = dk * __ldg(bp + (size_t)t * KK);
            float nr = fmaf(Ac, sr, fmaf(-Bc, si, gb));
            float ni = fmaf(Bc, sr, Ac * si);
            sr = nr; si = ni;
            sp[(size_t)t * (BB * KK)] = sr;
        }
    } else {
        __shared__ float nrs[KK], nis[KK];
        for (int t = 0; t < SS; t++) {
            float bt = __ldg(bp + (size_t)t * KK);
            float nr = fmaf(mag * cth, sr, fmaf(-mag * sth, si, bt));
            float ni = mag * fmaf(sr, sth, si * cth);
            nrs[k] = nr; nis[k] = ni;
            __syncthreads();
            float a0 = 0.0f, a1 = 0.0f;
            #pragma unroll 8
            for (int j = 0; j < KK; j++) {
                float rj = R[j * KK + k];
                a0 = fmaf(nrs[j], rj, a0);
                a1 = fmaf(nis[j], rj, a1);
            }
            __syncthreads();
            sr = a0; si = a1;
            sp[(size_t)t * (BB * KK)] = sr;
        }
    }
    srf[b * KK + k] = sr;
    sif[b * KK + k] = si;
}

// ============================================================================
// LayerNorm + transpose: row r = s*B + b of g_y -> out[b][s][:]
// ============================================================================
__global__ __launch_bounds__(256)
void ln_kernel(const float* __restrict__ g, const float* __restrict__ bb,
               float* __restrict__ out)
{
    const int r = blockIdx.x;
    const int t = threadIdx.x;

    const float4 v = ((const float4*)(g_y + (size_t)r * DD))[t];

    float sum = v.x + v.y + v.z + v.w;
    float sq  = fmaf(v.x, v.x, fmaf(v.y, v.y, fmaf(v.z, v.z, v.w * v.w)));

    #pragma unroll
    for (int o = 16; o > 0; o >>= 1) {
        sum += __shfl_xor_sync(0xffffffffu, sum, o);
        sq  += __shfl_xor_sync(0xffffffffu, sq,  o);
    }

    __shared__ float ssum[8], ssq[8];
    const int w = t >> 5, ln = t & 31;
    if (ln == 0) { ssum[w] = sum; ssq[w] = sq; }
    __syncthreads();
    if (t == 0) {
        float a = 0.0f, c2 = 0.0f;
        #pragma unroll
        for (int i = 0; i < 8; i++) { a += ssum[i]; c2 += ssq[i]; }
        ssum[0] = a; ssq[0] = c2;
    }
    __syncthreads();

    const float mu  = ssum[0] * (1.0f / DD);
    const float var = ssq[0] * (1.0f / DD) - mu * mu;
    const float inv = rsqrtf(var + LN_EPS);

    const float4 gg = ((const float4*)g)[t];
    const float4 b4 = ((const float4*)bb)[t];

    float4 o;
    o.x = fmaf((v.x - mu) * inv, gg.x, b4.x);
    o.y = fmaf((v.y - mu) * inv, gg.y, b4.y);
    o.z = fmaf((v.z - mu) * inv, gg.z, b4.z);
    o.w = fmaf((v.w - mu) * inv, gg.w, b4.w);

    const int s = r >> 3;
    const int b = r & 7;
    ((float4*)(out + ((size_t)b * SS + s) * DD))[t] = o;
}

// ============================================================================
// launch
// ============================================================================
extern "C" void kernel_launch(void* const* d_in, const int* in_sizes, int n_in,
                              void* d_out, int out_size)
{
    const float* x     = (const float*)d_in[0];  // (B,S,D)
    const float* alpha = (const float*)d_in[1];  // (K)
    const float* omega = (const float*)d_in[2];  // (K)
    const float* W_in  = (const float*)d_in[3];  // (K,D)
    const float* R     = (const float*)d_in[4];  // (K,K)
    const float* W_out = (const float*)d_in[5];  // (D,K)
    const float* b_out = (const float*)d_in[6];  // (D)
    const float* ln_g  = (const float*)d_in[7];  // (D)
    const float* ln_b  = (const float*)d_in[8];  // (D)

    float* out = (float*)d_out;                   // (B,S,D)
    float* srf = out + (size_t)BB * SS * DD;      // (B,K)
    float* sif = srf + (size_t)BB * KK;           // (B,K)

    float* beta_p;  cudaGetSymbolAddress((void**)&beta_p,  g_beta);
    float* srseq_p; cudaGetSymbolAddress((void**)&srseq_p, g_srseq);
    float* y_p;     cudaGetSymbolAddress((void**)&y_p,     g_y);

    const int SMEM = 4 * STG_F * (int)sizeof(float);   // 2 bufs x (A+B) = 73728 B
    cudaFuncSetAttribute(gemm_mma<1024>,
                         cudaFuncAttributeMaxDynamicSharedMemorySize, SMEM);
    cudaFuncSetAttribute(gemm_mma<128>,
                         cudaFuncAttributeMaxDynamicSharedMemorySize, SMEM);

    // 1) beta = x @ W_in^T : (32768 x 1024) * (128 x 1024)^T -> (32768 x 128)
    gemm_mma<1024><<<dim3(1, MM / 128), 256, SMEM>>>(x, W_in, beta_p, nullptr, KK);

    // 2) scan (parallel fast path + exact fallback; exactly one does work)
    scan_par<<<dim3(SCAN_NCH, BB), KK>>>(alpha, omega, R, srf, sif);
    scan_serial<<<BB, KK>>>(alpha, omega, R, srf, sif);

    // 3) y = sr_seq @ W_out^T + b_out : (32768 x 128) * (1024 x 128)^T -> (32768 x 1024)
    gemm_mma<128><<<dim3(DD / 128, MM / 128), 256, SMEM>>>(srseq_p, W_out, y_p, b_out, DD);

    // 4) LayerNorm + transpose to (B,S,D)
    ln_kernel<<<MM, 256>>>(ln_g, ln_b, out);
}